// round 8
// baseline (speedup 1.0000x reference)
#include <cuda_runtime.h>

#define D 1024
#define MAX_B 32
#define CHUNK 8
#define NBX 32
#define EPS 1e-6f

// 16-byte alignment REQUIRED: accessed as float4.
__device__ __align__(16) float g_state[MAX_B * D];   // zero at load; self-cleaning
__device__ __align__(16) float g_pool[MAX_B * D];
__device__ int g_arrive[MAX_B];                      // zero at load; self-cleaning
__device__ volatile int g_scan_done;                 // zero at load; self-cleaning
__device__ int g_fin;                                // zero at load; self-cleaning

__device__ __forceinline__ float warp_sum(float v) {
#pragma unroll
    for (int o = 16; o > 0; o >>= 1) v += __shfl_xor_sync(0xffffffffu, v, o);
    return v;
}

// ---- Single fused kernel: W-prefetch || scan -> grid sync -> GEMV ----
// grid (NBX, B) = 512 blocks, 256 threads. ALL blocks co-resident
// (launch_bounds(256,4): <=64 regs, <1KB smem) => spin-wait is safe.
__global__ void __launch_bounds__(256, 4)
fused_kernel(const float* __restrict__ x,
             const float* __restrict__ logit,
             const float* __restrict__ norm1_w,
             const float* __restrict__ norm2_w,
             const int* __restrict__ experts,
             const float* __restrict__ W,
             float* __restrict__ out,
             int S, int B, int E) {
    const int b = blockIdx.y;
    const int tid = threadIdx.x;    // 256
    const int d0 = tid * 4;
    const int wid = tid >> 5, lane = tid & 31;
    const int NTOT = gridDim.x * gridDim.y;   // 512

    // ---- gemm tile mapping + L2 prefetch of W tile (overlaps scan) ----
    const int flat  = blockIdx.y * gridDim.x + blockIdx.x;   // 0..511
    const int ntile = D / 8;                                  // 128 tiles/expert
    const int ge = flat / ntile;                              // expert
    const int gr = flat % ntile;                              // row tile
    const bool has_gemm = (ge < E);
    if (has_gemm) {
        const char* wp = (const char*)(W + ((size_t)ge * D + gr * 8) * D);
        asm volatile("prefetch.global.L2 [%0];" :: "l"(wp + tid * 128));
    }

    // ---- expert grouping (tiny, from input) ----
    __shared__ int s_bl[MAX_B];
    __shared__ int s_nb;
    {
        __shared__ int s_exp[MAX_B];
        if (tid < B) s_exp[tid] = experts[tid];
        __syncthreads();
        if (tid == 0) {
            int n = 0;
            for (int bb = 0; bb < B; bb++)
                if (s_exp[bb] == ge) s_bl[n++] = bb;
            s_nb = n;
        }
    }

    // ---- decay + truncation bound ----
    const float4 lg = *(const float4*)&logit[d0];
    float4 dc4;
    dc4.x = 1.f / (1.f + __expf(-lg.x));
    dc4.y = 1.f / (1.f + __expf(-lg.y));
    dc4.z = 1.f / (1.f + __expf(-lg.z));
    dc4.w = 1.f / (1.f + __expf(-lg.w));

    __shared__ float smax[8];
    float m = fmaxf(fmaxf(dc4.x, dc4.y), fmaxf(dc4.z, dc4.w));
#pragma unroll
    for (int o = 16; o > 0; o >>= 1) m = fmaxf(m, __shfl_xor_sync(0xffffffffu, m, o));
    if (lane == 0) smax[wid] = m;
    __syncthreads();
    float maxd = fmaxf(fmaxf(smax[0], smax[1]), fmaxf(smax[2], smax[3]));
    maxd = fmaxf(maxd, fmaxf(fmaxf(smax[4], smax[5]), fmaxf(smax[6], smax[7])));

    const int sch = (S + CHUNK - 1) / CHUNK;
    int nch;
    if (maxd >= 0.9999995f) {
        nch = sch;
    } else {
        float K = logf(1e-12f) / logf(maxd);
        int Ki = (int)K + 2;
        nch = (Ki + CHUNK - 1) / CHUNK;
        if (nch > sch) nch = sch;
        if (nch < 1) nch = 1;
    }

    // ---- scan phase ----
    float4 acc = make_float4(0.f, 0.f, 0.f, 0.f);
    bool did = false;

    __shared__ float sred[CHUNK][8];
    __shared__ float srstd[CHUNK];

    for (int c = blockIdx.x; c < nch; c += NBX) {
        did = true;
        const int t_hi = S - 1 - c * CHUNK;
        int t_lo = t_hi - (CHUNK - 1);
        if (t_lo < 0) t_lo = 0;
        const int valid = t_hi - t_lo + 1;
        const int e_min = c * CHUNK;

        const float* xb = x + ((size_t)b * S + t_hi) * D + d0;
        float4 xr[CHUNK];
#pragma unroll
        for (int i = 0; i < CHUNK; i++) {
            if (i < valid) xr[i] = *(const float4*)(xb - (size_t)i * D);
            else           xr[i] = make_float4(0.f, 0.f, 0.f, 0.f);
        }

#pragma unroll
        for (int i = 0; i < CHUNK; i++) {
            float4 v = xr[i];
            float s = warp_sum(v.x * v.x + v.y * v.y + v.z * v.z + v.w * v.w);
            if (lane == 0) sred[i][wid] = s;
        }
        __syncthreads();
        if (tid < CHUNK) {
            float s = 0.f;
#pragma unroll
            for (int w = 0; w < 8; w++) s += sred[tid][w];
            srstd[tid] = rsqrtf(s * (1.f / D) + EPS);
        }
        __syncthreads();

        float4 w4;
        w4.x = __powf(dc4.x, (float)e_min);
        w4.y = __powf(dc4.y, (float)e_min);
        w4.z = __powf(dc4.z, (float)e_min);
        w4.w = __powf(dc4.w, (float)e_min);

#pragma unroll
        for (int i = 0; i < CHUNK; i++) {
            if (i < valid) {
                float r = srstd[i];
                acc.x += w4.x * xr[i].x * r;
                acc.y += w4.y * xr[i].y * r;
                acc.z += w4.z * xr[i].z * r;
                acc.w += w4.w * xr[i].w * r;
            }
            w4.x *= dc4.x; w4.y *= dc4.y; w4.z *= dc4.z; w4.w *= dc4.w;
        }
        __syncthreads();   // sred reuse
    }

    float* gs = &g_state[b * D + d0];
    if (did) {
        const float4 nw = *(const float4*)&norm1_w[d0];
        atomicAdd(gs + 0, acc.x * nw.x * (1.f - dc4.x));
        atomicAdd(gs + 1, acc.y * nw.y * (1.f - dc4.y));
        atomicAdd(gs + 2, acc.z * nw.z * (1.f - dc4.z));
        atomicAdd(gs + 3, acc.w * nw.w * (1.f - dc4.w));
    }

    __threadfence();
    __shared__ int s_last;
    if (tid == 0)
        s_last = (atomicAdd(&g_arrive[b], 1) == NBX - 1);
    __syncthreads();

    if (s_last) {
        // pool = rmsnorm(x[b,S-1] + state, norm2_w); self-clean state/arrive
        const float4 xl = *(const float4*)(x + ((size_t)b * S + (S - 1)) * D + d0);
        const float4 st = __ldcg((const float4*)gs);
        float4 v = make_float4(xl.x + st.x, xl.y + st.y, xl.z + st.z, xl.w + st.w);

        *(float4*)gs = make_float4(0.f, 0.f, 0.f, 0.f);
        if (tid == 0) g_arrive[b] = 0;

        float s = warp_sum(v.x * v.x + v.y * v.y + v.z * v.z + v.w * v.w);
        __shared__ float sm2[8];
        __shared__ float srs;
        if (lane == 0) sm2[wid] = s;
        __syncthreads();
        if (tid == 0) {
            float t = 0.f;
#pragma unroll
            for (int w = 0; w < 8; w++) t += sm2[w];
            srs = rsqrtf(t * (1.f / D) + EPS);
        }
        __syncthreads();

        const float r = srs;
        const float4 n2 = *(const float4*)&norm2_w[d0];
        float4 p = make_float4(v.x * r * n2.x, v.y * r * n2.y,
                               v.z * r * n2.z, v.w * r * n2.w);
        *(float4*)&g_pool[b * D + d0] = p;
        __threadfence();
    }

    // ---- grid sync: counter == NTOT implies all pools written ----
    if (tid == 0) {
        atomicAdd((int*)&g_scan_done, 1);
        while (g_scan_done != NTOT) __nanosleep(64);
    }
    __syncthreads();

    // ---- gemm phase: 1 row/warp, batches of this block's expert ----
    if (has_gemm) {
        const int nb = s_nb;
        if (nb > 0) {
            const int row = gr * 8 + wid;
            const float* Wr = W + ((size_t)ge * D + row) * D;
            float4 w[8];
#pragma unroll
            for (int i = 0; i < 8; i++)
                w[i] = __ldg((const float4*)(Wr + i * 128 + lane * 4));

            for (int j = 0; j < nb; j++) {
                const float* pb = &g_pool[s_bl[j] * D];
                float a = 0.f;
#pragma unroll
                for (int i = 0; i < 8; i++) {
                    const float4 p = __ldg((const float4*)(pb + i * 128 + lane * 4));
                    a += w[i].x * p.x + w[i].y * p.y + w[i].z * p.z + w[i].w * p.w;
                }
                float s = warp_sum(a);
                if (lane == 0)
                    out[s_bl[j] * D + row] = fmaxf(s, 0.f);
            }
        }
    }

    // ---- self-clean sync counters (last finisher, within this launch) ----
    __syncthreads();
    if (tid == 0) {
        __threadfence();
        if (atomicAdd(&g_fin, 1) == NTOT - 1) {
            g_scan_done = 0;
            g_fin = 0;
        }
    }
}

// ---- Launch ----
extern "C" void kernel_launch(void* const* d_in, const int* in_sizes, int n_in,
                              void* d_out, int out_size) {
    const float* x        = (const float*)d_in[0];
    const int*   experts  = (const int*)d_in[1];
    const float* norm1_w  = (const float*)d_in[2];
    const float* tdl      = (const float*)d_in[3];
    const float* norm2_w  = (const float*)d_in[4];
    const float* W        = (const float*)d_in[5];
    float* out = (float*)d_out;

    const int B = in_sizes[1];
    const int S = in_sizes[0] / (B * D);
    const int E = in_sizes[5] / (D * D);

    dim3 grid(NBX, B);
    fused_kernel<<<grid, 256>>>(x, tdl, norm1_w, norm2_w, experts, W, out, S, B, E);
}

// round 9
// speedup vs baseline: 1.1030x; 1.1030x over previous
#include <cuda_runtime.h>

#define D 1024
#define MAX_B 32
#define CHUNK 8
#define GRP 4
#define NBX 32
#define EPS 1e-6f
#define TRUNC 1e-9f

// 16-byte alignment REQUIRED: accessed as float4.
__device__ __align__(16) float g_state[MAX_B * D];   // zero at load; self-cleaning
__device__ __align__(16) float g_pool[MAX_B * D];
__device__ int g_arrive[MAX_B];                      // zero at load; self-cleaning

__device__ __forceinline__ float warp_sum(float v) {
#pragma unroll
    for (int o = 16; o > 0; o >>= 1) v += __shfl_xor_sync(0xffffffffu, v, o);
    return v;
}

// ---- Kernel 1: truncated decay-weighted scan + fused pool rmsnorm ----
__global__ void scan_kernel(const float* __restrict__ x,
                            const float* __restrict__ logit,
                            const float* __restrict__ norm1_w,
                            const float* __restrict__ norm2_w, int S) {
    const int b = blockIdx.y;
    const int tid = threadIdx.x;    // 256
    const int d0 = tid * 4;
    const int wid = tid >> 5, lane = tid & 31;

    // ---- chunk 0 loads FIRST: hide the decay prologue under memory ----
    const int c0 = blockIdx.x;
    int t_hi0 = S - 1 - c0 * CHUNK;
    float4 xr[CHUNK];
    int valid0 = 0;
    if (t_hi0 >= 0) {
        int t_lo = t_hi0 - (CHUNK - 1);
        if (t_lo < 0) t_lo = 0;
        valid0 = t_hi0 - t_lo + 1;
        const float* xb = x + ((size_t)b * S + t_hi0) * D + d0;
#pragma unroll
        for (int i = 0; i < CHUNK; i++)
            xr[i] = (i < valid0) ? *(const float4*)(xb - (size_t)i * D)
                                 : make_float4(0.f, 0.f, 0.f, 0.f);
    } else {
#pragma unroll
        for (int i = 0; i < CHUNK; i++) xr[i] = make_float4(0.f, 0.f, 0.f, 0.f);
    }

    // ---- decay prologue (overlapped with the loads above) ----
    const float4 lg = *(const float4*)&logit[d0];
    float4 dc4;
    dc4.x = 1.f / (1.f + __expf(-lg.x));
    dc4.y = 1.f / (1.f + __expf(-lg.y));
    dc4.z = 1.f / (1.f + __expf(-lg.z));
    dc4.w = 1.f / (1.f + __expf(-lg.w));

    __shared__ float smax[8];
    float m = fmaxf(fmaxf(dc4.x, dc4.y), fmaxf(dc4.z, dc4.w));
#pragma unroll
    for (int o = 16; o > 0; o >>= 1) m = fmaxf(m, __shfl_xor_sync(0xffffffffu, m, o));
    if (lane == 0) smax[wid] = m;
    __syncthreads();
    float maxd = fmaxf(fmaxf(smax[0], smax[1]), fmaxf(smax[2], smax[3]));
    maxd = fmaxf(maxd, fmaxf(fmaxf(smax[4], smax[5]), fmaxf(smax[6], smax[7])));

    const int sch = (S + CHUNK - 1) / CHUNK;
    int nch;
    if (maxd >= 0.9999995f) {
        nch = sch;
    } else {
        float K = logf(TRUNC) / logf(maxd);
        int Ki = (int)K + 2;
        nch = (Ki + CHUNK - 1) / CHUNK;
        if (nch > sch) nch = sch;
        if (nch < 1) nch = 1;
    }

    float4 acc = make_float4(0.f, 0.f, 0.f, 0.f);
    bool did = false;

    __shared__ float sred[CHUNK][8];
    __shared__ float srstd[CHUNK];

    for (int c = c0; c < nch; c += NBX) {
        did = true;
        const int t_hi = S - 1 - c * CHUNK;
        int t_lo = t_hi - (CHUNK - 1);
        if (t_lo < 0) t_lo = 0;
        const int valid = t_hi - t_lo + 1;
        const int e_min = c * CHUNK;

        if (c != c0) {   // chunk 0 already in registers
            const float* xb = x + ((size_t)b * S + t_hi) * D + d0;
#pragma unroll
            for (int i = 0; i < CHUNK; i++)
                xr[i] = (i < valid) ? *(const float4*)(xb - (size_t)i * D)
                                    : make_float4(0.f, 0.f, 0.f, 0.f);
        }

#pragma unroll
        for (int i = 0; i < CHUNK; i++) {
            float4 v = xr[i];
            float s = warp_sum(v.x * v.x + v.y * v.y + v.z * v.z + v.w * v.w);
            if (lane == 0) sred[i][wid] = s;
        }
        __syncthreads();
        if (tid < CHUNK) {
            float s = 0.f;
#pragma unroll
            for (int w = 0; w < 8; w++) s += sred[tid][w];
            srstd[tid] = rsqrtf(s * (1.f / D) + EPS);
        }
        __syncthreads();

        float4 w4;
        w4.x = __powf(dc4.x, (float)e_min);
        w4.y = __powf(dc4.y, (float)e_min);
        w4.z = __powf(dc4.z, (float)e_min);
        w4.w = __powf(dc4.w, (float)e_min);

#pragma unroll
        for (int i = 0; i < CHUNK; i++) {
            if (i < valid) {
                float r = srstd[i];
                acc.x += w4.x * xr[i].x * r;
                acc.y += w4.y * xr[i].y * r;
                acc.z += w4.z * xr[i].z * r;
                acc.w += w4.w * xr[i].w * r;
            }
            w4.x *= dc4.x; w4.y *= dc4.y; w4.z *= dc4.z; w4.w *= dc4.w;
        }
        __syncthreads();   // sred reuse
    }

    float* gs = &g_state[b * D + d0];
    if (did) {
        const float4 nw = *(const float4*)&norm1_w[d0];
        atomicAdd(gs + 0, acc.x * nw.x * (1.f - dc4.x));
        atomicAdd(gs + 1, acc.y * nw.y * (1.f - dc4.y));
        atomicAdd(gs + 2, acc.z * nw.z * (1.f - dc4.z));
        atomicAdd(gs + 3, acc.w * nw.w * (1.f - dc4.w));
    }

    __threadfence();
    __shared__ int s_last;
    if (tid == 0)
        s_last = (atomicAdd(&g_arrive[b], 1) == NBX - 1);
    __syncthreads();
    if (!s_last) return;

    const float4 xl = *(const float4*)(x + ((size_t)b * S + (S - 1)) * D + d0);
    const float4 st = __ldcg((const float4*)gs);
    float4 v = make_float4(xl.x + st.x, xl.y + st.y, xl.z + st.z, xl.w + st.w);

    *(float4*)gs = make_float4(0.f, 0.f, 0.f, 0.f);   // self-clean for replay
    if (tid == 0) g_arrive[b] = 0;

    float s = warp_sum(v.x * v.x + v.y * v.y + v.z * v.z + v.w * v.w);
    __shared__ float sm2[8];
    __shared__ float srs;
    if (lane == 0) sm2[wid] = s;
    __syncthreads();
    if (tid == 0) {
        float t = 0.f;
#pragma unroll
        for (int w = 0; w < 8; w++) t += sm2[w];
        srs = rsqrtf(t * (1.f / D) + EPS);
    }
    __syncthreads();

    const float r = srs;
    const float4 n2 = *(const float4*)&norm2_w[d0];
    float4 p = make_float4(v.x * r * n2.x, v.y * r * n2.y,
                           v.z * r * n2.z, v.w * r * n2.w);
    *(float4*)&g_pool[b * D + d0] = p;
}

// ---- Kernel 2: expert GEMV. W loads FIRST (MLP=8 hides grouping prologue),
//      then internal loop over batch groups with smem pool staging. ----
__global__ void gemm_kernel(const int* __restrict__ experts,
                            const float* __restrict__ W,
                            float* __restrict__ out, int B) {
    const int e = blockIdx.y;
    const int tid = threadIdx.x;   // 256
    const int warp = tid >> 5, lane = tid & 31;

    // W row: 8 independent LDG.128 issued before anything else
    const int row = blockIdx.x * 8 + warp;
    const float* Wr = W + ((size_t)e * D + row) * D;
    float4 w[8];
#pragma unroll
    for (int i = 0; i < 8; i++)
        w[i] = __ldg((const float4*)(Wr + i * 128 + lane * 4));

    // expert grouping (overlapped with W loads)
    __shared__ int s_exp[MAX_B];
    __shared__ int s_bl[MAX_B];
    __shared__ int s_nb;
    if (tid < B) s_exp[tid] = experts[tid];
    __syncthreads();
    if (tid == 0) {
        int n = 0;
        for (int b = 0; b < B; b++)
            if (s_exp[b] == e) s_bl[n++] = b;
        s_nb = n;
    }
    __syncthreads();
    const int nb = s_nb;
    if (nb == 0) return;

    __shared__ __align__(16) float s_pool[GRP][D];   // 16 KB

    for (int base = 0; base < nb; base += GRP) {
        const int cnt = min(GRP, nb - base);
        if (base) __syncthreads();      // protect s_pool reuse
#pragma unroll
        for (int j = 0; j < GRP; j++) {
            float4 p = make_float4(0.f, 0.f, 0.f, 0.f);
            if (j < cnt) p = *(const float4*)&g_pool[s_bl[base + j] * D + tid * 4];
            *(float4*)&s_pool[j][tid * 4] = p;
        }
        __syncthreads();

        float acc[GRP] = {0.f, 0.f, 0.f, 0.f};
#pragma unroll
        for (int i = 0; i < 8; i++) {
#pragma unroll
            for (int j = 0; j < GRP; j++) {
                const float4 p = *(const float4*)&s_pool[j][i * 128 + lane * 4];
                acc[j] += w[i].x * p.x + w[i].y * p.y + w[i].z * p.z + w[i].w * p.w;
            }
        }

#pragma unroll
        for (int j = 0; j < GRP; j++) {
            float s = warp_sum(acc[j]);
            if (lane == 0 && j < cnt)
                out[s_bl[base + j] * D + row] = fmaxf(s, 0.f);
        }
    }
}

// ---- Launch ----
extern "C" void kernel_launch(void* const* d_in, const int* in_sizes, int n_in,
                              void* d_out, int out_size) {
    const float* x        = (const float*)d_in[0];
    const int*   experts  = (const int*)d_in[1];
    const float* norm1_w  = (const float*)d_in[2];
    const float* tdl      = (const float*)d_in[3];
    const float* norm2_w  = (const float*)d_in[4];
    const float* W        = (const float*)d_in[5];
    float* out = (float*)d_out;

    const int B = in_sizes[1];
    const int S = in_sizes[0] / (B * D);
    const int E = in_sizes[5] / (D * D);

    dim3 gscan(NBX, B);
    scan_kernel<<<gscan, 256>>>(x, tdl, norm1_w, norm2_w, S);

    dim3 ggemm(D / 8, E);
    gemm_kernel<<<ggemm, 256>>>(experts, W, out, B);
}